// round 2
// baseline (speedup 1.0000x reference)
#include <cuda_runtime.h>
#include <math.h>

typedef unsigned long long u64;

// ---------------- problem constants ----------------
#define NB   64      // batch
#define NCQ  5       // candidates per sample
#define LQ   20      // question length
#define NF   20      // video frames
#define CIN  8192    // video feature dim
#define EMB  300     // embedding dim
#define HID  512     // LSTM hidden
#define G4   2048    // 4*HID
#define RT   320     // NB*NCQ

// ---------------- device scratch (allocation-free) ----------------
__device__ float g_Xv[(size_t)NF * NB * G4];   // [t][b][gate]  (bias folded)
__device__ float g_Xt[(size_t)LQ * RT * G4];   // [t][r][gate]  (bias folded)
__device__ float g_vh[2][2][NB * HID];         // [layer][parity]
__device__ float g_vc[2][2][NB * HID];
__device__ float g_vcand[NB * HID];
__device__ float g_th[2][2][RT * HID];
__device__ float g_tc[2][2][RT * HID];
__device__ float g_tcand[RT * HID];
__device__ float g_vec[2 * HID];
__device__ float g_cnst;
__device__ unsigned g_cnt = 0;
__device__ unsigned g_gen = 0;

// ---------------- helpers ----------------
__device__ __forceinline__ u64 ffma2(u64 a, u64 b, u64 c) {
    u64 d;
    asm("fma.rn.f32x2 %0, %1, %2, %3;" : "=l"(d) : "l"(a), "l"(b), "l"(c));
    return d;
}

__device__ __forceinline__ float sigf(float x) {
    return 1.0f / (1.0f + __expf(-x));
}

// grid-wide barrier: monotonically increasing generation counter, safe across
// CUDA-graph replays (no state that must be reset between launches except the
// count, which every barrier resets itself).
__device__ __forceinline__ void grid_sync(unsigned nb) {
    __syncthreads();
    if (threadIdx.x == 0) {
        __threadfence();
        unsigned gen = g_gen;
        if (atomicAdd(&g_cnt, 1u) == nb - 1u) {
            g_cnt = 0;
            __threadfence();
            atomicAdd(&g_gen, 1u);
        } else {
            while (*(volatile unsigned*)&g_gen == gen) { __nanosleep(32); }
        }
        __threadfence();
    }
    __syncthreads();
}

// ==================================================================
// Input GEMM:  C[r][g] = bias[g] + sum_k A_row(r)[k] * W[g][k]
//   mode 0 (video): r = t*64+b, A_row = video + (b*NF+t)*CIN, K=8192, C=g_Xv
//   mode 1 (text) : r = t*320+rr, qid = questions[rr*LQ+t],
//                   A_row = embed + qid*EMB, K=300, C=g_Xt
// Tile 64x64, BK=32, 256 threads, 4x4 micro (strided rows/gates), f32x2.
// ==================================================================
__global__ void __launch_bounds__(256) in_gemm_kernel(
    const float* __restrict__ Abase, const int* __restrict__ qidx,
    const float* __restrict__ W, const float* __restrict__ bias,
    int K, int mode, int ntn)
{
    __shared__ float As[64 * 34];
    __shared__ float Bs[64 * 34];

    float* C = mode ? g_Xt : g_Xv;

    int tm = blockIdx.x / ntn, tn = blockIdx.x % ntn;
    int m0 = tm * 64, n0 = tn * 64;
    int tid = threadIdx.x;
    int tx = tid & 15, ty = tid >> 4;

    // fixed per-thread load rows (2 positions: tid, tid+256)
    const float* arow[2];
    const float* wrow[2];
    int akq[2];
    #pragma unroll
    for (int s = 0; s < 2; s++) {
        int p = tid + s * 256;
        int rloc = p >> 3;
        akq[s] = (p & 7) * 4;
        int r = m0 + rloc;
        if (mode == 0) {
            int t = r >> 6, b = r & 63;
            arow[s] = Abase + (size_t)(b * NF + t) * CIN;
        } else {
            int rr = r % RT, t = r / RT;
            int qid = qidx[rr * LQ + t];
            arow[s] = Abase + (size_t)qid * EMB;
        }
        wrow[s] = W + (size_t)(n0 + rloc) * K;
    }

    u64 acc[4][4];
    #pragma unroll
    for (int i = 0; i < 4; i++)
        #pragma unroll
        for (int j = 0; j < 4; j++) acc[i][j] = 0ull;

    for (int kb = 0; kb < K; kb += 32) {
        bool full = (kb + 32 <= K);
        #pragma unroll
        for (int s = 0; s < 2; s++) {
            int p = tid + s * 256;
            int rloc = p >> 3;
            int kq = akq[s];
            float a0, a1, a2v, a3, w0, w1, w2v, w3;
            if (full) {
                float4 av = *(const float4*)(arow[s] + kb + kq);
                float4 wv = *(const float4*)(wrow[s] + kb + kq);
                a0 = av.x; a1 = av.y; a2v = av.z; a3 = av.w;
                w0 = wv.x; w1 = wv.y; w2v = wv.z; w3 = wv.w;
            } else {
                int k0 = kb + kq;
                a0 = (k0 + 0 < K) ? arow[s][k0 + 0] : 0.0f;
                a1 = (k0 + 1 < K) ? arow[s][k0 + 1] : 0.0f;
                a2v = (k0 + 2 < K) ? arow[s][k0 + 2] : 0.0f;
                a3 = (k0 + 3 < K) ? arow[s][k0 + 3] : 0.0f;
                w0 = (k0 + 0 < K) ? wrow[s][k0 + 0] : 0.0f;
                w1 = (k0 + 1 < K) ? wrow[s][k0 + 1] : 0.0f;
                w2v = (k0 + 2 < K) ? wrow[s][k0 + 2] : 0.0f;
                w3 = (k0 + 3 < K) ? wrow[s][k0 + 3] : 0.0f;
            }
            float* da = &As[rloc * 34 + kq];
            *(float2*)(da)     = make_float2(a0, a1);
            *(float2*)(da + 2) = make_float2(a2v, a3);
            float* db = &Bs[rloc * 34 + kq];
            *(float2*)(db)     = make_float2(w0, w1);
            *(float2*)(db + 2) = make_float2(w2v, w3);
        }
        __syncthreads();
        #pragma unroll
        for (int kk = 0; kk < 16; kk++) {
            u64 a2[4], b2[4];
            #pragma unroll
            for (int i = 0; i < 4; i++)
                a2[i] = *(const u64*)&As[(tx + 16 * i) * 34 + 2 * kk];
            #pragma unroll
            for (int j = 0; j < 4; j++)
                b2[j] = *(const u64*)&Bs[(ty + 16 * j) * 34 + 2 * kk];
            #pragma unroll
            for (int i = 0; i < 4; i++)
                #pragma unroll
                for (int j = 0; j < 4; j++)
                    acc[i][j] = ffma2(a2[i], b2[j], acc[i][j]);
        }
        __syncthreads();
    }

    #pragma unroll
    for (int i = 0; i < 4; i++) {
        int r = m0 + tx + 16 * i;
        #pragma unroll
        for (int j = 0; j < 4; j++) {
            int g = n0 + ty + 16 * j;
            union { u64 u; float2 f; } v; v.u = acc[i][j];
            C[(size_t)r * G4 + g] = v.f.x + v.f.y + bias[g];
        }
    }
}

// ==================================================================
// One fused LSTM layer stage (GEMM over K=512 or 1024 + cell update),
// used inside the persistent recurrence kernels.
//   gates[r][g] = (Xadd? Xadd[r][g]:0) + (bias? bias[g]:0)
//              + sum_k A1[r][k]*W1[g][k] + (A2? sum_k A2[r][k]*W2[g][k] :0)
// Tile: BM rows x 64 gates where the 64 gates = 16 j-columns x 4 quadrants
// (i,f,g,o). Thread (tx,ty) holds all 4 quadrants of column j0+ty for its 4
// rows -> fully thread-local cell update.
// ==================================================================
template <int BM>
__device__ __forceinline__ void lstm_stage(
    float* As, float* Bs,
    const float* __restrict__ A1, const float* __restrict__ W1,
    const float* __restrict__ A2, const float* __restrict__ W2,
    const float* __restrict__ Xadd, const float* __restrict__ bias,
    const float* __restrict__ hOld, const float* __restrict__ cOld,
    float* __restrict__ hNew, float* __restrict__ cNew,
    float* __restrict__ hCand,
    const int* __restrict__ qlen, int t, int R)
{
    const int TXN = BM / 4;        // thread rows dimension
    const int THREADS = BM * 4;
    int tid = threadIdx.x;
    int tx = tid % TXN, ty = tid / TXN;
    int rowTiles = R / BM;
    int nTiles = rowTiles * 32;

    for (int tile = blockIdx.x; tile < nTiles; tile += gridDim.x) {
        int m0 = (tile >> 5) * BM;
        int j0 = (tile & 31) * 16;

        u64 acc[4][4];
        #pragma unroll
        for (int i = 0; i < 4; i++)
            #pragma unroll
            for (int j = 0; j < 4; j++) acc[i][j] = 0ull;

        int Ktot = A2 ? 1024 : 512;
        for (int kb = 0; kb < Ktot; kb += 32) {
            const float* Ak; const float* Wk; int ko;
            if (kb < 512) { Ak = A1; Wk = W1; ko = kb; }
            else          { Ak = A2; Wk = W2; ko = kb - 512; }

            // A tile (state -> must bypass L1 across SMs)
            #pragma unroll
            for (int s = 0; s < 2; s++) {
                int p = tid + s * THREADS;
                int rloc = p >> 3;
                int kq = (p & 7) * 4;
                float4 av = __ldcg((const float4*)(Ak + (size_t)(m0 + rloc) * HID + ko + kq));
                float* d = &As[rloc * 34 + kq];
                *(float2*)(d)     = make_float2(av.x, av.y);
                *(float2*)(d + 2) = make_float2(av.z, av.w);
            }
            // W tile (constant weights, quadrant-remapped gate rows)
            for (int p = tid; p < 512; p += THREADS) {
                int lg = p >> 3;
                int kq = (p & 7) * 4;
                int gate = (lg >> 4) * HID + j0 + (lg & 15);
                float4 wv = *(const float4*)(Wk + (size_t)gate * HID + ko + kq);
                float* d = &Bs[lg * 34 + kq];
                *(float2*)(d)     = make_float2(wv.x, wv.y);
                *(float2*)(d + 2) = make_float2(wv.z, wv.w);
            }
            __syncthreads();
            #pragma unroll
            for (int kk = 0; kk < 16; kk++) {
                u64 a2[4], b2[4];
                #pragma unroll
                for (int i = 0; i < 4; i++)
                    a2[i] = *(const u64*)&As[(tx + TXN * i) * 34 + 2 * kk];
                #pragma unroll
                for (int j = 0; j < 4; j++)
                    b2[j] = *(const u64*)&Bs[(ty + 16 * j) * 34 + 2 * kk];
                #pragma unroll
                for (int i = 0; i < 4; i++)
                    #pragma unroll
                    for (int j = 0; j < 4; j++)
                        acc[i][j] = ffma2(a2[i], b2[j], acc[i][j]);
            }
            __syncthreads();
        }

        // fused LSTM cell epilogue (quadrants are this thread's j-outputs)
        int j = j0 + ty;
        #pragma unroll
        for (int i = 0; i < 4; i++) {
            int r = m0 + tx + TXN * i;
            float gv[4];
            #pragma unroll
            for (int q = 0; q < 4; q++) {
                union { u64 u; float2 f; } v; v.u = acc[i][q];
                float x = v.f.x + v.f.y;
                if (Xadd) x += Xadd[(size_t)r * G4 + q * HID + j];
                if (bias) x += bias[q * HID + j];
                gv[q] = x;
            }
            float co = __ldcg(&cOld[r * HID + j]);
            float ig = sigf(gv[0]);
            float fg = sigf(gv[1]);
            float gg = tanhf(gv[2]);
            float og = sigf(gv[3]);
            float cn = fg * co + ig * gg;
            float hc = og * tanhf(cn);
            bool up = true;
            if (qlen) up = (t < __ldg(&qlen[r / NCQ]));
            float hn, cw;
            if (up) { hn = hc; cw = cn; }
            else    { hn = __ldcg(&hOld[r * HID + j]); cw = co; }
            if (hCand) hCand[r * HID + j] = hc;
            hNew[r * HID + j] = hn;
            cNew[r * HID + j] = cw;
        }
    }
}

// ---------------- persistent video recurrence (20 steps, 2 layers) ----------------
__global__ void __launch_bounds__(128) vrec_kernel(
    const float* __restrict__ Whh1, const float* __restrict__ Wih2,
    const float* __restrict__ Whh2, const float* __restrict__ bias2)
{
    __shared__ float As[32 * 34];
    __shared__ float Bs[64 * 34];
    unsigned nb = gridDim.x;

    // init states (parity 0) to zero
    for (int i = blockIdx.x * blockDim.x + threadIdx.x; i < NB * HID;
         i += gridDim.x * blockDim.x) {
        g_vh[0][0][i] = 0.0f; g_vc[0][0][i] = 0.0f;
        g_vh[1][0][i] = 0.0f; g_vc[1][0][i] = 0.0f;
    }
    grid_sync(nb);

    for (int t = 0; t < NF; t++) {
        int p = t & 1;
        // layer 1: gates = Xv[t] + h1 @ Whh_v1^T  (bias folded into Xv)
        lstm_stage<32>(As, Bs,
                       g_vh[0][p], Whh1, nullptr, nullptr,
                       g_Xv + (size_t)t * NB * G4, nullptr,
                       g_vh[0][p], g_vc[0][p],
                       g_vh[0][1 - p], g_vc[0][1 - p], g_vcand,
                       nullptr, 0, NB);
        grid_sync(nb);
        // layer 2: gates = b_v2 + h1cand @ Wih_v2^T + h2 @ Whh_v2^T
        lstm_stage<32>(As, Bs,
                       g_vcand, Wih2, g_vh[1][p], Whh2,
                       nullptr, bias2,
                       g_vh[1][p], g_vc[1][p],
                       g_vh[1][1 - p], g_vc[1][1 - p], nullptr,
                       nullptr, 0, NB);
        grid_sync(nb);
    }
}

// ---------------- persistent text recurrence (masked, 20 steps, 2 layers) ----------------
__global__ void __launch_bounds__(256) trec_kernel(
    const float* __restrict__ Whh1, const float* __restrict__ Wih2,
    const float* __restrict__ Whh2, const float* __restrict__ bias2,
    const int* __restrict__ qlen)
{
    __shared__ float As[64 * 34];
    __shared__ float Bs[64 * 34];
    unsigned nb = gridDim.x;

    // init: broadcast final video states (parity 0 after 20 steps) to NC copies
    for (int i = blockIdx.x * blockDim.x + threadIdx.x; i < RT * HID;
         i += gridDim.x * blockDim.x) {
        int r = i >> 9;           // /HID
        int j = i & (HID - 1);
        int b = r / NCQ;
        int src = b * HID + j;
        g_th[0][0][i] = g_vh[0][0][src];
        g_tc[0][0][i] = g_vc[0][0][src];
        g_th[1][0][i] = g_vh[1][0][src];
        g_tc[1][0][i] = g_vc[1][0][src];
    }
    grid_sync(nb);

    for (int t = 0; t < LQ; t++) {
        int p = t & 1;
        lstm_stage<64>(As, Bs,
                       g_th[0][p], Whh1, nullptr, nullptr,
                       g_Xt + (size_t)t * RT * G4, nullptr,
                       g_th[0][p], g_tc[0][p],
                       g_th[0][1 - p], g_tc[0][1 - p], g_tcand,
                       qlen, t, RT);
        grid_sync(nb);
        lstm_stage<64>(As, Bs,
                       g_tcand, Wih2, g_th[1][p], Whh2,
                       nullptr, bias2,
                       g_th[1][p], g_tc[1][p],
                       g_th[1][1 - p], g_tc[1][1 - p], nullptr,
                       qlen, t, RT);
        grid_sync(nb);
    }
}

// ---------------- decoder collapse: v[k] = sum_m dec2_w[m]*dec1_w[m][k] ----------------
__global__ void __launch_bounds__(1024) dec_vec_kernel(
    const float* __restrict__ d1w, const float* __restrict__ d1b,
    const float* __restrict__ d2w, const float* __restrict__ d2b)
{
    __shared__ float red[1024];
    int k = threadIdx.x;
    float s = 0.0f;
    for (int m = 0; m < 1024; m++) s += d2w[m] * d1w[m * 1024 + k];
    g_vec[k] = s;
    red[k] = d2w[k] * d1b[k];
    __syncthreads();
    for (int off = 512; off > 0; off >>= 1) {
        if (k < off) red[k] += red[k + off];
        __syncthreads();
    }
    if (k == 0) g_cnst = red[0] + d2b[0];
}

// ---------------- final outputs + argmax ----------------
__global__ void __launch_bounds__(256) dec_out_kernel(float* __restrict__ out,
                                                      int out_size)
{
    int b = blockIdx.x;
    int tid = threadIdx.x;
    __shared__ float red[256];
    __shared__ float vals[NCQ];

    for (int nc = 0; nc < NCQ; nc++) {
        int r = b * NCQ + nc;
        float s = 0.0f;
        for (int k = tid; k < 2 * HID; k += 256) {
            float sv = (k < HID) ? g_th[0][0][r * HID + k]
                                 : g_th[1][0][r * HID + (k - HID)];
            s += sv * g_vec[k];
        }
        red[tid] = s;
        __syncthreads();
        for (int off = 128; off > 0; off >>= 1) {
            if (tid < off) red[tid] += red[tid + off];
            __syncthreads();
        }
        if (tid == 0) vals[nc] = red[0] + g_cnst;
        __syncthreads();
    }

    if (tid == 0) {
        float best = vals[0];
        int bi = 0;
        #pragma unroll
        for (int nc = 0; nc < NCQ; nc++) {
            out[b * NCQ + nc] = vals[nc];
            if (vals[nc] > best) { best = vals[nc]; bi = nc; }
        }
        if (out_size >= RT + NB) out[RT + b] = (float)bi;
    }
}

// ==================================================================
extern "C" void kernel_launch(void* const* d_in, const int* in_sizes, int n_in,
                              void* d_out, int out_size)
{
    const float* video  = (const float*)d_in[0];
    const int*   quest  = (const int*)  d_in[1];
    const int*   qlen   = (const int*)  d_in[2];
    const float* embed  = (const float*)d_in[3];
    const float* Wih_t1 = (const float*)d_in[4];
    const float* Whh_t1 = (const float*)d_in[5];
    const float* b_t1   = (const float*)d_in[6];
    const float* Wih_t2 = (const float*)d_in[7];
    const float* Whh_t2 = (const float*)d_in[8];
    const float* b_t2   = (const float*)d_in[9];
    const float* Wih_v1 = (const float*)d_in[10];
    const float* Whh_v1 = (const float*)d_in[11];
    const float* b_v1   = (const float*)d_in[12];
    const float* Wih_v2 = (const float*)d_in[13];
    const float* Whh_v2 = (const float*)d_in[14];
    const float* b_v2   = (const float*)d_in[15];
    const float* d1w    = (const float*)d_in[16];
    const float* d1b    = (const float*)d_in[17];
    const float* d2w    = (const float*)d_in[18];
    const float* d2b    = (const float*)d_in[19];
    float* out = (float*)d_out;

    // 1) hoisted input GEMMs (fully parallel)
    //    video: rows = NF*NB = 1280 -> 20 x 32 tiles
    in_gemm_kernel<<<20 * 32, 256>>>(video, nullptr, Wih_v1, b_v1, CIN, 0, 32);
    //    text: rows = LQ*RT = 6400 -> 100 x 32 tiles
    in_gemm_kernel<<<100 * 32, 256>>>(embed, quest, Wih_t1, b_t1, EMB, 1, 32);

    // 2) decoder collapse (independent of recurrences)
    dec_vec_kernel<<<1, 1024>>>(d1w, d1b, d2w, d2b);

    // 3) video recurrence (persistent, grid barrier)
    vrec_kernel<<<64, 128>>>(Whh_v1, Wih_v2, Whh_v2, b_v2);

    // 4) text recurrence (persistent, masked)
    trec_kernel<<<128, 256>>>(Whh_t1, Wih_t2, Whh_t2, b_t2, qlen);

    // 5) outputs + argmax
    dec_out_kernel<<<NB, 256>>>(out, out_size);
}

// round 4
// speedup vs baseline: 1.2567x; 1.2567x over previous
#include <cuda_runtime.h>
#include <math.h>

// ---------------- problem constants ----------------
#define NB   64
#define NCQ  5
#define LQ   20
#define NF   20
#define CIN  8192
#define EMB  300
#define EMBP 304      // padded
#define HID  512
#define G4   2048
#define RT   320

// ---------------- device scratch ----------------
__device__ float g_vidc[(size_t)NB * NF * CIN];      // tf32-rounded video
__device__ float g_embc[(size_t)8000 * EMBP];        // tf32-rounded embed (padded)
__device__ float g_Wv1re[(size_t)G4 * CIN];          // reordered tf32 weights
__device__ float g_Wt1re[(size_t)G4 * EMBP];
__device__ float g_Whv1re[(size_t)G4 * HID];
__device__ float g_Wiv2re[(size_t)G4 * HID];
__device__ float g_Whv2re[(size_t)G4 * HID];
__device__ float g_Wht1re[(size_t)G4 * HID];
__device__ float g_Wit2re[(size_t)G4 * HID];
__device__ float g_Wht2re[(size_t)G4 * HID];
__device__ float g_bv1re[G4];
__device__ float g_bt1re[G4];
__device__ float g_bv2re[G4];
__device__ float g_bt2re[G4];

__device__ float g_Xv[(size_t)NF * NB * G4];         // [t][b][n], n=j*4+q
__device__ float g_Xt[(size_t)LQ * RT * G4];
__device__ float g_vh[2][2][NB * HID];
__device__ float g_vc[2][2][NB * HID];
__device__ float g_vcand[NB * HID];
__device__ float g_th[2][2][RT * HID];
__device__ float g_tc[2][2][RT * HID];
__device__ float g_tcand[RT * HID];
__device__ float g_vec[2 * HID];
__device__ float g_cnst;
__device__ unsigned g_cnt = 0;
__device__ unsigned g_gen = 0;

// ---------------- helpers ----------------
__device__ __forceinline__ float tf32r(float x) {
    unsigned u;
    asm("cvt.rna.tf32.f32 %0, %1;" : "=r"(u) : "f"(x));
    return __uint_as_float(u);
}
__device__ __forceinline__ unsigned fbits(float x) { return __float_as_uint(x); }

__device__ __forceinline__ void mma8(float* c, unsigned a0, unsigned a1,
                                     unsigned a2, unsigned a3,
                                     unsigned b0, unsigned b1) {
    asm volatile(
        "mma.sync.aligned.m16n8k8.row.col.f32.tf32.tf32.f32 "
        "{%0,%1,%2,%3}, {%4,%5,%6,%7}, {%8,%9}, {%0,%1,%2,%3};"
        : "+f"(c[0]), "+f"(c[1]), "+f"(c[2]), "+f"(c[3])
        : "r"(a0), "r"(a1), "r"(a2), "r"(a3), "r"(b0), "r"(b1));
}

__device__ __forceinline__ float sigf(float x) {
    return 1.0f / (1.0f + __expf(-x));
}

// grid-wide barrier: generation counter, monotone across graph replays
__device__ __forceinline__ void grid_sync(unsigned nb) {
    __syncthreads();
    if (threadIdx.x == 0) {
        __threadfence();
        unsigned gen = g_gen;
        if (atomicAdd(&g_cnt, 1u) == nb - 1u) {
            g_cnt = 0;
            __threadfence();
            atomicAdd(&g_gen, 1u);
        } else {
            while (*(volatile unsigned*)&g_gen == gen) { __nanosleep(32); }
        }
        __threadfence();
    }
    __syncthreads();
}

// ---------------- prep kernels ----------------
__global__ void prep_cvt(const float* __restrict__ src, float* __restrict__ dst, int n) {
    for (int i = blockIdx.x * blockDim.x + threadIdx.x; i < n;
         i += gridDim.x * blockDim.x)
        dst[i] = tf32r(src[i]);
}
__global__ void prep_pad(const float* __restrict__ src, float* __restrict__ dst,
                         int rows, int K, int Kpad) {
    int n = rows * Kpad;
    for (int i = blockIdx.x * blockDim.x + threadIdx.x; i < n;
         i += gridDim.x * blockDim.x) {
        int r = i / Kpad, k = i - r * Kpad;
        dst[i] = (k < K) ? tf32r(src[r * K + k]) : 0.0f;
    }
}
// reorder gate rows: dst[(j*4+q)][Kpad] = cvt(src[(q*512+j)][K])
__global__ void prep_reorder(const float* __restrict__ src, float* __restrict__ dst,
                             int K, int Kpad) {
    int n = G4 * Kpad;
    for (int i = blockIdx.x * blockDim.x + threadIdx.x; i < n;
         i += gridDim.x * blockDim.x) {
        int nn = i / Kpad, k = i - nn * Kpad;
        int j = nn >> 2, q = nn & 3;
        dst[i] = (k < K) ? tf32r(src[(size_t)(q * HID + j) * K + k]) : 0.0f;
    }
}
__global__ void prep_bias(const float* b1, const float* b2,
                          const float* b3, const float* b4) {
    for (int nn = blockIdx.x * blockDim.x + threadIdx.x; nn < G4;
         nn += gridDim.x * blockDim.x) {
        int j = nn >> 2, q = nn & 3;
        int gidx = q * HID + j;
        g_bv1re[nn] = b1[gidx];
        g_bt1re[nn] = b2[gidx];
        g_bv2re[nn] = b3[gidx];
        g_bt2re[nn] = b4[gidx];
    }
}

// ==================================================================
// Input GEMM (tf32 mma): C[r][n] = biasre[n] + sum_k A(r)[k]*Wre[n][k]
// BM=BN=128, BK=16, 256 thr, warps 4x2, warp tile 32x64.
// ==================================================================
__global__ void __launch_bounds__(256) in_gemm_tf32(
    const float* __restrict__ Abase, const int* __restrict__ qidx,
    const float* __restrict__ Wre, const float* __restrict__ biasre,
    float* __restrict__ C, int Kpad, int mode, int ntn)
{
    __shared__ float As[128][20];
    __shared__ float Bs[128][20];

    int tm = blockIdx.x / ntn, tn = blockIdx.x % ntn;
    int m0 = tm * 128, n0 = tn * 128;
    int tid = threadIdx.x;
    int w = tid >> 5, lane = tid & 31;
    int rg = w >> 1, cg = w & 1;
    int g = lane >> 2, tg = lane & 3;
    int cq = (tid & 3) * 4;

    const float* aptr[2];
    const float* wptr[2];
    #pragma unroll
    for (int s = 0; s < 2; s++) {
        int rloc = (tid >> 2) + s * 64;
        int r = m0 + rloc;
        if (mode == 0) {
            int t = r >> 6, b = r & 63;
            aptr[s] = Abase + (size_t)(b * NF + t) * Kpad;
        } else {
            int rr = r % RT, t = r / RT;
            int qid = qidx[rr * LQ + t];
            aptr[s] = Abase + (size_t)qid * Kpad;
        }
        wptr[s] = Wre + (size_t)(n0 + rloc) * Kpad;
    }

    float acc[2][8][4];
    #pragma unroll
    for (int mi = 0; mi < 2; mi++)
        #pragma unroll
        for (int nc = 0; nc < 8; nc++)
            #pragma unroll
            for (int v = 0; v < 4; v++) acc[mi][nc][v] = 0.0f;

    int niter = Kpad / 16;
    for (int it = 0; it < niter; it++) {
        int kb = it * 16;
        #pragma unroll
        for (int s = 0; s < 2; s++) {
            int rloc = (tid >> 2) + s * 64;
            *(float4*)&As[rloc][cq] = *(const float4*)(aptr[s] + kb + cq);
            *(float4*)&Bs[rloc][cq] = *(const float4*)(wptr[s] + kb + cq);
        }
        __syncthreads();
        #pragma unroll
        for (int ks = 0; ks < 2; ks++) {
            unsigned a[2][4];
            #pragma unroll
            for (int mi = 0; mi < 2; mi++) {
                int ar = rg * 32 + mi * 16;
                a[mi][0] = fbits(As[ar + g][ks * 8 + tg]);
                a[mi][1] = fbits(As[ar + g + 8][ks * 8 + tg]);
                a[mi][2] = fbits(As[ar + g][ks * 8 + tg + 4]);
                a[mi][3] = fbits(As[ar + g + 8][ks * 8 + tg + 4]);
            }
            #pragma unroll
            for (int nc = 0; nc < 8; nc++) {
                int nr = cg * 64 + nc * 8 + g;
                unsigned b0 = fbits(Bs[nr][ks * 8 + tg]);
                unsigned b1 = fbits(Bs[nr][ks * 8 + tg + 4]);
                #pragma unroll
                for (int mi = 0; mi < 2; mi++)
                    mma8(acc[mi][nc], a[mi][0], a[mi][1], a[mi][2], a[mi][3], b0, b1);
            }
        }
        __syncthreads();
    }

    #pragma unroll
    for (int nc = 0; nc < 8; nc++) {
        int col = n0 + cg * 64 + nc * 8 + 2 * tg;
        float2 bb = *(const float2*)(biasre + col);
        #pragma unroll
        for (int mi = 0; mi < 2; mi++) {
            int row0 = m0 + rg * 32 + mi * 16 + g;
            *(float2*)(C + (size_t)row0 * G4 + col) =
                make_float2(acc[mi][nc][0] + bb.x, acc[mi][nc][1] + bb.y);
            *(float2*)(C + (size_t)(row0 + 8) * G4 + col) =
                make_float2(acc[mi][nc][2] + bb.x, acc[mi][nc][3] + bb.y);
        }
    }
}

// ==================================================================
// Fused LSTM stage (tf32 mma + cell update).
// Block tile: 16*RG rows x 32 j (=128 reordered gate cols). Warps RG x 2,
// warp tile 16 rows x 64 gate-cols (4 quadrants x 16 j).
// ==================================================================
template <int RG>
__device__ __forceinline__ void stage_mma(
    float* As /*[16*RG][20]*/, float* Bs /*[128][17]*/,
    const float* __restrict__ A1, const float* __restrict__ W1,
    const float* __restrict__ A2, const float* __restrict__ W2,
    const float* __restrict__ Xadd, const float* __restrict__ biasre,
    const float* __restrict__ hOld, const float* __restrict__ cOld,
    float* __restrict__ hNew, float* __restrict__ cNew,
    float* __restrict__ hCand,
    const int* __restrict__ qlen, int t, int m0, int j0)
{
    const int NT = 64 * RG;
    int tid = threadIdx.x;
    int w = tid >> 5, lane = tid & 31;
    int rg = w >> 1, jg = w & 1;
    int g = lane >> 2, tg = lane & 3;

    float acc[8][4];
    #pragma unroll
    for (int ch = 0; ch < 8; ch++)
        #pragma unroll
        for (int v = 0; v < 4; v++) acc[ch][v] = 0.0f;

    int iters = A2 ? 64 : 32;
    for (int it = 0; it < iters; it++) {
        int kb = it * 16;
        const float* Asrc; const float* Wsrc; int ko;
        if (kb < HID) { Asrc = A1; Wsrc = W1; ko = kb; }
        else          { Asrc = A2; Wsrc = W2; ko = kb - HID; }

        {   // A fill: 1 float4/thread, cvt to tf32 (state is fp32)
            int rloc = tid >> 2, acq = (tid & 3) * 4;
            float4 v = __ldcg((const float4*)(Asrc + (size_t)(m0 + rloc) * HID + ko + acq));
            float* d = As + rloc * 20 + acq;
            d[0] = tf32r(v.x); d[1] = tf32r(v.y); d[2] = tf32r(v.z); d[3] = tf32r(v.w);
        }
        // B fill: weights already tf32-rounded/reordered
        for (int s = tid; s < 512; s += NT) {
            int nloc = s >> 2, bcq = (s & 3) * 4;
            float4 v = *(const float4*)(Wsrc + (size_t)(j0 * 4 + nloc) * HID + ko + bcq);
            float* d = Bs + nloc * 17 + bcq;
            d[0] = v.x; d[1] = v.y; d[2] = v.z; d[3] = v.w;
        }
        __syncthreads();
        #pragma unroll
        for (int ks = 0; ks < 2; ks++) {
            int ar = rg * 16;
            unsigned a0 = fbits(As[(ar + g) * 20 + ks * 8 + tg]);
            unsigned a1 = fbits(As[(ar + g + 8) * 20 + ks * 8 + tg]);
            unsigned a2 = fbits(As[(ar + g) * 20 + ks * 8 + tg + 4]);
            unsigned a3 = fbits(As[(ar + g + 8) * 20 + ks * 8 + tg + 4]);
            #pragma unroll
            for (int ch = 0; ch < 8; ch++) {
                int q = ch >> 1, jh = ch & 1;
                int n = (jg * 16 + jh * 8 + g) * 4 + q;
                unsigned b0 = fbits(Bs[n * 17 + ks * 8 + tg]);
                unsigned b1 = fbits(Bs[n * 17 + ks * 8 + tg + 4]);
                mma8(acc[ch], a0, a1, a2, a3, b0, b1);
            }
        }
        __syncthreads();
    }

    // fused LSTM cell epilogue
    #pragma unroll
    for (int rs = 0; rs < 2; rs++) {
        int r = m0 + rg * 16 + g + rs * 8;
        bool up = qlen ? (t < __ldg(&qlen[r / NCQ])) : true;
        #pragma unroll
        for (int jh = 0; jh < 2; jh++) {
            int jb = j0 + jg * 16 + jh * 8 + 2 * tg;
            float2 co = __ldcg((const float2*)(cOld + (size_t)r * HID + jb));
            float2 ho = __ldcg((const float2*)(hOld + (size_t)r * HID + jb));
            float rh[2], rc[2], rcd[2];
            #pragma unroll
            for (int cp = 0; cp < 2; cp++) {
                int j = jb + cp;
                float iv = acc[0 + jh][rs * 2 + cp];
                float fv = acc[2 + jh][rs * 2 + cp];
                float gv = acc[4 + jh][rs * 2 + cp];
                float ov = acc[6 + jh][rs * 2 + cp];
                if (Xadd) {
                    float4 x = *(const float4*)(Xadd + (size_t)r * G4 + j * 4);
                    iv += x.x; fv += x.y; gv += x.z; ov += x.w;
                }
                if (biasre) {
                    float4 bx = *(const float4*)(biasre + j * 4);
                    iv += bx.x; fv += bx.y; gv += bx.z; ov += bx.w;
                }
                float cold = cp ? co.y : co.x;
                float ig = sigf(iv), fg = sigf(fv);
                float gt = tanhf(gv), og = sigf(ov);
                float cn = fg * cold + ig * gt;
                float hc = og * tanhf(cn);
                rcd[cp] = hc;
                rh[cp] = up ? hc : (cp ? ho.y : ho.x);
                rc[cp] = up ? cn : cold;
            }
            if (hCand)
                *(float2*)(hCand + (size_t)r * HID + jb) = make_float2(rcd[0], rcd[1]);
            *(float2*)(hNew + (size_t)r * HID + jb) = make_float2(rh[0], rh[1]);
            *(float2*)(cNew + (size_t)r * HID + jb) = make_float2(rc[0], rc[1]);
        }
    }
}

// ---------------- persistent video recurrence: 32 blocks x 128 thr ----------------
__global__ void __launch_bounds__(128) vrec_kernel()
{
    __shared__ float As[32 * 20];
    __shared__ float Bs[128 * 17];
    unsigned nb = gridDim.x;
    int m0 = (blockIdx.x >> 4) * 32;   // 2 row tiles of 32
    int j0 = (blockIdx.x & 15) * 32;   // 16 j tiles

    for (int i = blockIdx.x * blockDim.x + threadIdx.x; i < NB * HID;
         i += gridDim.x * blockDim.x) {
        g_vh[0][0][i] = 0.0f; g_vc[0][0][i] = 0.0f;
        g_vh[1][0][i] = 0.0f; g_vc[1][0][i] = 0.0f;
    }
    grid_sync(nb);

    for (int t = 0; t < NF; t++) {
        int p = t & 1;
        stage_mma<2>(As, Bs,
                     g_vh[0][p], g_Whv1re, nullptr, nullptr,
                     g_Xv + (size_t)t * NB * G4, nullptr,
                     g_vh[0][p], g_vc[0][p],
                     g_vh[0][1 - p], g_vc[0][1 - p], g_vcand,
                     nullptr, 0, m0, j0);
        grid_sync(nb);
        stage_mma<2>(As, Bs,
                     g_vcand, g_Wiv2re, g_vh[1][p], g_Whv2re,
                     nullptr, g_bv2re,
                     g_vh[1][p], g_vc[1][p],
                     g_vh[1][1 - p], g_vc[1][1 - p], nullptr,
                     nullptr, 0, m0, j0);
        grid_sync(nb);
    }
}

// ---------------- persistent text recurrence: 80 blocks x 256 thr ----------------
__global__ void __launch_bounds__(256) trec_kernel(const int* __restrict__ qlen)
{
    __shared__ float As[64 * 20];
    __shared__ float Bs[128 * 17];
    unsigned nb = gridDim.x;
    int m0 = (blockIdx.x >> 4) * 64;   // 5 row tiles of 64
    int j0 = (blockIdx.x & 15) * 32;   // 16 j tiles

    for (int i = blockIdx.x * blockDim.x + threadIdx.x; i < RT * HID;
         i += gridDim.x * blockDim.x) {
        int r = i >> 9;
        int j = i & (HID - 1);
        int src = (r / NCQ) * HID + j;
        g_th[0][0][i] = g_vh[0][0][src];
        g_tc[0][0][i] = g_vc[0][0][src];
        g_th[1][0][i] = g_vh[1][0][src];
        g_tc[1][0][i] = g_vc[1][0][src];
    }
    grid_sync(nb);

    for (int t = 0; t < LQ; t++) {
        int p = t & 1;
        stage_mma<4>(As, Bs,
                     g_th[0][p], g_Wht1re, nullptr, nullptr,
                     g_Xt + (size_t)t * RT * G4, nullptr,
                     g_th[0][p], g_tc[0][p],
                     g_th[0][1 - p], g_tc[0][1 - p], g_tcand,
                     qlen, t, m0, j0);
        grid_sync(nb);
        stage_mma<4>(As, Bs,
                     g_tcand, g_Wit2re, g_th[1][p], g_Wht2re,
                     nullptr, g_bt2re,
                     g_th[1][p], g_tc[1][p],
                     g_th[1][1 - p], g_tc[1][1 - p], nullptr,
                     qlen, t, m0, j0);
        grid_sync(nb);
    }
}

// ---------------- decoder collapse ----------------
__global__ void __launch_bounds__(1024) dec_vec_kernel(
    const float* __restrict__ d1w, const float* __restrict__ d1b,
    const float* __restrict__ d2w, const float* __restrict__ d2b)
{
    __shared__ float red[1024];
    int k = threadIdx.x;
    float s = 0.0f;
    for (int m = 0; m < 1024; m++) s += d2w[m] * d1w[m * 1024 + k];
    g_vec[k] = s;
    red[k] = d2w[k] * d1b[k];
    __syncthreads();
    for (int off = 512; off > 0; off >>= 1) {
        if (k < off) red[k] += red[k + off];
        __syncthreads();
    }
    if (k == 0) g_cnst = red[0] + d2b[0];
}

// ---------------- outputs + argmax ----------------
__global__ void __launch_bounds__(256) dec_out_kernel(float* __restrict__ out,
                                                      int out_size)
{
    int b = blockIdx.x;
    int tid = threadIdx.x;
    __shared__ float red[256];
    __shared__ float vals[NCQ];

    for (int nc = 0; nc < NCQ; nc++) {
        int r = b * NCQ + nc;
        float s = 0.0f;
        for (int k = tid; k < 2 * HID; k += 256) {
            float sv = (k < HID) ? g_th[0][0][r * HID + k]
                                 : g_th[1][0][r * HID + (k - HID)];
            s += sv * g_vec[k];
        }
        red[tid] = s;
        __syncthreads();
        for (int off = 128; off > 0; off >>= 1) {
            if (tid < off) red[tid] += red[tid + off];
            __syncthreads();
        }
        if (tid == 0) vals[nc] = red[0] + g_cnst;
        __syncthreads();
    }

    if (tid == 0) {
        float best = vals[0];
        int bi = 0;
        #pragma unroll
        for (int nc = 0; nc < NCQ; nc++) {
            out[b * NCQ + nc] = vals[nc];
            if (vals[nc] > best) { best = vals[nc]; bi = nc; }
        }
        if (out_size >= RT + NB) out[RT + b] = (float)bi;
    }
}

// ==================================================================
extern "C" void kernel_launch(void* const* d_in, const int* in_sizes, int n_in,
                              void* d_out, int out_size)
{
    const float* video  = (const float*)d_in[0];
    const int*   quest  = (const int*)  d_in[1];
    const int*   qlen   = (const int*)  d_in[2];
    const float* embed  = (const float*)d_in[3];
    const float* Wih_t1 = (const float*)d_in[4];
    const float* Whh_t1 = (const float*)d_in[5];
    const float* b_t1   = (const float*)d_in[6];
    const float* Wih_t2 = (const float*)d_in[7];
    const float* Whh_t2 = (const float*)d_in[8];
    const float* b_t2   = (const float*)d_in[9];
    const float* Wih_v1 = (const float*)d_in[10];
    const float* Whh_v1 = (const float*)d_in[11];
    const float* b_v1   = (const float*)d_in[12];
    const float* Wih_v2 = (const float*)d_in[13];
    const float* Whh_v2 = (const float*)d_in[14];
    const float* b_v2   = (const float*)d_in[15];
    const float* d1w    = (const float*)d_in[16];
    const float* d1b    = (const float*)d_in[17];
    const float* d2w    = (const float*)d_in[18];
    const float* d2b    = (const float*)d_in[19];
    float* out = (float*)d_out;

    float* pvid;  cudaGetSymbolAddress((void**)&pvid,  g_vidc);
    float* pemb;  cudaGetSymbolAddress((void**)&pemb,  g_embc);
    float* pWv1;  cudaGetSymbolAddress((void**)&pWv1,  g_Wv1re);
    float* pWt1;  cudaGetSymbolAddress((void**)&pWt1,  g_Wt1re);
    float* pWhv1; cudaGetSymbolAddress((void**)&pWhv1, g_Whv1re);
    float* pWiv2; cudaGetSymbolAddress((void**)&pWiv2, g_Wiv2re);
    float* pWhv2; cudaGetSymbolAddress((void**)&pWhv2, g_Whv2re);
    float* pWht1; cudaGetSymbolAddress((void**)&pWht1, g_Wht1re);
    float* pWit2; cudaGetSymbolAddress((void**)&pWit2, g_Wit2re);
    float* pWht2; cudaGetSymbolAddress((void**)&pWht2, g_Wht2re);
    float* pbv1;  cudaGetSymbolAddress((void**)&pbv1,  g_bv1re);
    float* pbt1;  cudaGetSymbolAddress((void**)&pbt1,  g_bt1re);
    float* pXv;   cudaGetSymbolAddress((void**)&pXv,   g_Xv);
    float* pXt;   cudaGetSymbolAddress((void**)&pXt,   g_Xt);

    // ---- prep: tf32 rounding + gate-row reorder ----
    prep_cvt    <<<2048, 256>>>(video, pvid, NB * NF * CIN);
    prep_pad    <<<2048, 256>>>(embed, pemb, 8000, EMB, EMBP);
    prep_reorder<<<4096, 256>>>(Wih_v1, pWv1, CIN, CIN);
    prep_reorder<<<1024, 256>>>(Wih_t1, pWt1, EMB, EMBP);
    prep_reorder<<<1024, 256>>>(Whh_v1, pWhv1, HID, HID);
    prep_reorder<<<1024, 256>>>(Wih_v2, pWiv2, HID, HID);
    prep_reorder<<<1024, 256>>>(Whh_v2, pWhv2, HID, HID);
    prep_reorder<<<1024, 256>>>(Whh_t1, pWht1, HID, HID);
    prep_reorder<<<1024, 256>>>(Wih_t2, pWit2, HID, HID);
    prep_reorder<<<1024, 256>>>(Whh_t2, pWht2, HID, HID);
    prep_bias   <<<8, 256>>>(b_v1, b_t1, b_v2, b_t2);

    // ---- hoisted input GEMMs ----
    in_gemm_tf32<<<10 * 16, 256>>>(pvid, nullptr, pWv1, pbv1, pXv, CIN, 0, 16);
    in_gemm_tf32<<<50 * 16, 256>>>(pemb, quest, pWt1, pbt1, pXt, EMBP, 1, 16);

    // ---- decoder collapse ----
    dec_vec_kernel<<<1, 1024>>>(d1w, d1b, d2w, d2b);

    // ---- recurrences ----
    vrec_kernel<<<32, 128>>>();
    trec_kernel<<<80, 256>>>(qlen);

    // ---- outputs ----
    dec_out_kernel<<<NB, 256>>>(out, out_size);
}